// round 11
// baseline (speedup 1.0000x reference)
#include <cuda_runtime.h>
#include <cuda_bf16.h>
#include <stdint.h>

// Problem constants (TokenSelector: B=32, D=256, H=W=64)
#define BB 32
#define DD 256
#define NN 4096          // H*W
#define KK 2048          // NN * KEEP_RATIO

#define SCORE_BLKS 16            // score blocks per batch
#define GATH_BLKS  128           // gather blocks per batch
#define BLKS_PER_B (SCORE_BLKS + 1 + GATH_BLKS)   // 145

// ---------------- scratch (device globals; no allocation allowed) ----------
__device__ unsigned g_keys[BB * NN];
__device__ int      g_pos [BB * NN];
__device__ int      g_sync[64];   // [0..31] score counters, [32..63] select flags

// float -> monotone-increasing uint key
__device__ __forceinline__ unsigned f2k(float f) {
    unsigned u = __float_as_uint(f);
    return u ^ ((u >> 31) ? 0xFFFFFFFFu : 0x80000000u);
}

// ============================================================================
// ROLE 1: score — per-token ordering key. score = rstd*(dot(x,w')-mu*sum(w'))
// (softmax / norm_b / fc_b are order-irrelevant). Thread owns a quad of 4
// consecutive tokens over a 64-wide d-slice (4 splits); warp reads 512B
// contiguous per LDG.128, 4 batched. (Measured standalone: 24.4us.)
// ============================================================================
__device__ __forceinline__ void score_role(
    const float* __restrict__ tokens, const float* __restrict__ norm_w,
    const float* __restrict__ fc_w, unsigned* __restrict__ keys,
    int b, int bx, char* sm)
{
    float*  wsh = (float*)sm;                 // 1KB
    float4* r1  = (float4*)(sm + 1024);       // 4KB
    float4* r2  = (float4*)(sm + 5120);       // 4KB
    float4* r3  = (float4*)(sm + 9216);       // 4KB
    float*  rw  = (float*)(sm + 13312);       // 1KB

    const int tid   = threadIdx.x;
    const int q     = tid & 63;
    const int split = tid >> 6;

    wsh[tid] = norm_w[tid] * fc_w[tid];
    __syncthreads();

    const int n4 = bx * 64 + q;
    const float4* p = (const float4*)(tokens + (size_t)b * DD * NN) + n4;

    float4 s1 = {0.f,0.f,0.f,0.f}, s2 = s1, sd = s1;
    float  sw = 0.f;
#pragma unroll
    for (int j0 = 0; j0 < 64; j0 += 4) {
        float4 x[4];
#pragma unroll
        for (int jj = 0; jj < 4; ++jj)
            x[jj] = p[(size_t)(split * 64 + j0 + jj) * (NN / 4)];
#pragma unroll
        for (int jj = 0; jj < 4; ++jj) {
            float w = wsh[split * 64 + j0 + jj];
            s1.x += x[jj].x;           s1.y += x[jj].y;
            s1.z += x[jj].z;           s1.w += x[jj].w;
            s2.x += x[jj].x * x[jj].x; s2.y += x[jj].y * x[jj].y;
            s2.z += x[jj].z * x[jj].z; s2.w += x[jj].w * x[jj].w;
            sd.x += x[jj].x * w;       sd.y += x[jj].y * w;
            sd.z += x[jj].z * w;       sd.w += x[jj].w * w;
            sw   += w;
        }
    }
    if (split != 0) {
        r1[split * 64 + q] = s1; r2[split * 64 + q] = s2;
        r3[split * 64 + q] = sd; rw[split * 64 + q] = sw;
    }
    __syncthreads();

    if (split == 0) {
#pragma unroll
        for (int s = 1; s < 4; ++s) {
            float4 a = r1[s * 64 + q], c = r2[s * 64 + q], d = r3[s * 64 + q];
            s1.x += a.x; s1.y += a.y; s1.z += a.z; s1.w += a.w;
            s2.x += c.x; s2.y += c.y; s2.z += c.z; s2.w += c.w;
            sd.x += d.x; sd.y += d.y; sd.z += d.z; sd.w += d.w;
            sw   += rw[s * 64 + q];
        }
        const float inv = 1.0f / (float)DD;
        uint4 kv;
        float mu, var;
        mu = s1.x*inv; var = fmaxf(s2.x*inv - mu*mu, 0.f);
        kv.x = f2k((sd.x - mu*sw) * rsqrtf(var + 1e-5f));
        mu = s1.y*inv; var = fmaxf(s2.y*inv - mu*mu, 0.f);
        kv.y = f2k((sd.y - mu*sw) * rsqrtf(var + 1e-5f));
        mu = s1.z*inv; var = fmaxf(s2.z*inv - mu*mu, 0.f);
        kv.z = f2k((sd.z - mu*sw) * rsqrtf(var + 1e-5f));
        mu = s1.w*inv; var = fmaxf(s2.w*inv - mu*mu, 0.f);
        kv.w = f2k((sd.w - mu*sw) * rsqrtf(var + 1e-5f));
        ((uint4*)keys)[b * (NN / 4) + n4] = kv;
    }
}

// ============================================================================
// ROLE 2: select — per-batch radix-select (KK-th largest) + rank compaction.
// 256 threads, 16 keys/thread. Warp-aggregated histogram atomics, parallel
// suffix-scan bin pick, packed shuffle-scan compaction. lax.top_k tie rules.
// ============================================================================
__device__ __forceinline__ void select_role(
    const unsigned* __restrict__ keys, int* __restrict__ pos, int b, char* sm)
{
    int*      hist     = (int*)sm;
    int*      wsum     = (int*)(sm + 1024);
    unsigned* s_prefix = (unsigned*)(sm + 1056);
    int*      s_R      = (int*)(sm + 1060);

    const int tid  = threadIdx.x;
    const int lane = tid & 31;
    const int wid  = tid >> 5;

    unsigned k[16];
#pragma unroll
    for (int i = 0; i < 4; ++i) {
        uint4 kv = ((const uint4*)(keys + b * NN))[tid * 4 + i];
        k[i*4+0] = kv.x; k[i*4+1] = kv.y; k[i*4+2] = kv.z; k[i*4+3] = kv.w;
    }
    if (tid == 0) { *s_prefix = 0u; *s_R = KK; }
    __syncthreads();

    unsigned mask = 0u;
    for (int shift = 24; shift >= 0; shift -= 8) {
        hist[tid] = 0;
        __syncthreads();
        const unsigned prefix = *s_prefix;
        const int      R      = *s_R;

#pragma unroll
        for (int j = 0; j < 16; ++j) {
            int bin = ((k[j] & mask) == prefix) ? (int)((k[j] >> shift) & 255u) : 256;
            unsigned mm  = __match_any_sync(0xFFFFFFFFu, bin);
            int      ldr = __ffs(mm) - 1;
            if (lane == ldr && bin < 256)
                atomicAdd(&hist[bin], __popc(mm));
        }
        __syncthreads();

        int c = hist[255 - tid];
        int v = c;
#pragma unroll
        for (int o = 1; o < 32; o <<= 1) {
            int t = __shfl_up_sync(0xFFFFFFFFu, v, o);
            if (lane >= o) v += t;
        }
        if (lane == 31) wsum[wid] = v;
        __syncthreads();
        int S = v;
#pragma unroll
        for (int w = 0; w < 7; ++w)
            if (w < wid) S += wsum[w];
        if (S >= R && S - c < R) {                 // unique boundary thread
            *s_prefix = prefix | ((unsigned)(255 - tid) << shift);
            *s_R      = R - (S - c);
        }
        mask |= 255u << shift;
        __syncthreads();
    }
    const unsigned T    = *s_prefix;
    const int      Rfin = *s_R;

    int cg = 0, ce = 0;
#pragma unroll
    for (int j = 0; j < 16; ++j) { cg += (k[j] > T); ce += (k[j] == T); }
    int myv = (cg << 16) | ce;
    int v = myv;
#pragma unroll
    for (int o = 1; o < 32; o <<= 1) {
        int t = __shfl_up_sync(0xFFFFFFFFu, v, o);
        if (lane >= o) v += t;
    }
    if (lane == 31) wsum[wid] = v;
    __syncthreads();
    if (wid == 0 && lane < 8) {
        int t = wsum[lane];
#pragma unroll
        for (int o = 1; o < 8; o <<= 1) {
            int u = __shfl_up_sync(0x000000FFu, t, o);
            if (lane >= o) t += u;
        }
        wsum[lane] = t;
    }
    __syncthreads();
    int pre = v - myv + (wid > 0 ? wsum[wid - 1] : 0);
    int g = pre >> 16;
    int e = pre & 0xFFFF;

    int vals[16];
#pragma unroll
    for (int j = 0; j < 16; ++j) {
        int kp = -1;
        if (k[j] > T)       { kp = g + min(e, Rfin); ++g; }
        else if (k[j] == T) { if (e < Rfin) kp = g + e; ++e; }
        vals[j] = kp;
    }
#pragma unroll
    for (int i = 0; i < 4; ++i) {
        int4 op = { vals[i*4+0], vals[i*4+1], vals[i*4+2], vals[i*4+3] };
        ((int4*)(pos + b * NN))[tid * 4 + i] = op;
    }
}

// ============================================================================
// ROLE 3: gather — streaming compaction. 32 tokens x D in two d-halves,
// 128x33 tile (17KB), float4 loads (L2-hot: batch b was just streamed by
// score), conflict-free smem both directions, __stcs writes.
// ============================================================================
__device__ __forceinline__ void gather_role(
    const float* __restrict__ tokens, const int* __restrict__ pos,
    float* __restrict__ out, int b, int bx, char* sm)
{
    float (*tile)[33] = (float(*)[33])sm;     // 16896B
    int*   spos       = (int*)(sm + 16896);   // 128B

    const int tid = threadIdx.x;
    const int n0  = bx * 32;

    if (tid < 32) spos[tid] = pos[b * NN + n0 + tid];

    const int f  = tid & 7;
    const int d0 = tid >> 3;
    const float* base = tokens + (size_t)b * DD * NN + n0 + f * 4;
    float* ob = out + (size_t)b * KK * DD;

    const int kk2 = tid >> 7;
    const int c   = tid & 127;

#pragma unroll
    for (int h = 0; h < 2; ++h) {
        __syncthreads();                      // tile reuse guard + spos vis
#pragma unroll
        for (int j = 0; j < 4; ++j) {
            int d = d0 + j * 32;
            float4 v = *(const float4*)(base + (size_t)(h * 128 + d) * NN);
            tile[d][f * 4 + 0] = v.x;
            tile[d][f * 4 + 1] = v.y;
            tile[d][f * 4 + 2] = v.z;
            tile[d][f * 4 + 3] = v.w;
        }
        __syncthreads();
#pragma unroll
        for (int pair = 0; pair < 16; ++pair) {
            int kk = pair * 2 + kk2;
            int p  = spos[kk];
            if (p >= 0)
                __stcs(&ob[(size_t)p * DD + h * 128 + c], tile[c][kk]);
        }
    }
}

// ============================================================================
// Single-launch dataflow pipeline. Blocks ordered [S(b)x16, Sel(b), G(b)x128]
// per batch; per-batch deps via release/acquire atomics. A block only ever
// waits on LOWER-indexed blocks; CLC dispatches in index order -> no deadlock.
// Hardware scheduler overlaps score(b+1..) with gather(b): blended DRAM
// streams + gather(b) reads batch b's 4MB while still L2-resident.
// ============================================================================
__global__ void __launch_bounds__(256)
pipeline_kernel(const float* __restrict__ tokens,
                const float* __restrict__ norm_w,
                const float* __restrict__ fc_w,
                unsigned*    __restrict__ keys,
                int*         __restrict__ pos,
                float*       __restrict__ out)
{
    __shared__ __align__(16) char sm[17408];

    const int idx = blockIdx.x;
    const int b   = idx / BLKS_PER_B;
    const int r   = idx - b * BLKS_PER_B;

    if (r < SCORE_BLKS) {
        score_role(tokens, norm_w, fc_w, keys, b, r, sm);
        __syncthreads();
        __threadfence();                              // release keys
        if (threadIdx.x == 0) atomicAdd(&g_sync[b], 1);
    } else if (r == SCORE_BLKS) {
        if (threadIdx.x == 0)
            while (atomicAdd(&g_sync[b], 0) < SCORE_BLKS) __nanosleep(64);
        __syncthreads();
        __threadfence();                              // acquire keys
        select_role(keys, pos, b, sm);
        __syncthreads();
        __threadfence();                              // release pos
        if (threadIdx.x == 0) atomicExch(&g_sync[32 + b], 1);
    } else {
        if (threadIdx.x == 0)
            while (atomicAdd(&g_sync[32 + b], 0) == 0) __nanosleep(64);
        __syncthreads();
        __threadfence();                              // acquire pos
        gather_role(tokens, pos, out, b, r - SCORE_BLKS - 1, sm);
    }
}

// ---------------------------------------------------------------------------
extern "C" void kernel_launch(void* const* d_in, const int* in_sizes, int n_in,
                              void* d_out, int out_size)
{
    const float* tokens = (const float*)d_in[0];
    const float* norm_w = (const float*)d_in[1];
    // d_in[2] = norm_b (order-irrelevant constant shift)
    const float* fc_w   = (const float*)d_in[3];
    // d_in[4] = fc_b   (order-irrelevant constant shift)
    float* out = (float*)d_out;

    unsigned* keys;
    int* pos;
    int* sync;
    cudaGetSymbolAddress((void**)&keys, g_keys);
    cudaGetSymbolAddress((void**)&pos,  g_pos);
    cudaGetSymbolAddress((void**)&sync, g_sync);

    cudaMemsetAsync(sync, 0, 64 * sizeof(int));       // reset pipeline state
    pipeline_kernel<<<BB * BLKS_PER_B, 256>>>(tokens, norm_w, fc_w,
                                              keys, pos, out);
}

// round 12
// speedup vs baseline: 1.1966x; 1.1966x over previous
#include <cuda_runtime.h>
#include <cuda_bf16.h>
#include <stdint.h>

// Problem constants (TokenSelector: B=32, D=256, H=W=64)
#define BB 32
#define DD 256
#define NN 4096          // H*W
#define KK 2048          // NN * KEEP_RATIO

#define SCORE_BLKS 16            // score blocks per batch
#define GATH_BLKS  128           // gather blocks per batch
#define BLKS_PER_B (SCORE_BLKS + 1 + GATH_BLKS)   // 145

// ---------------- scratch (device globals; no allocation allowed) ----------
__device__ unsigned g_keys[BB * NN];
__device__ int      g_pos [BB * NN];
__device__ int      g_sync[64];   // [0..31] score counters, [32..63] select flags

// float -> monotone-increasing uint key
__device__ __forceinline__ unsigned f2k(float f) {
    unsigned u = __float_as_uint(f);
    return u ^ ((u >> 31) ? 0xFFFFFFFFu : 0x80000000u);
}

// ============================================================================
// ROLE 1: score — per-token ordering key. score = rstd*(dot(x,w')-mu*sum(w'))
// (softmax / norm_b / fc_b are order-irrelevant). Thread owns a quad of 4
// consecutive tokens over a 64-wide d-slice (4 splits); warp reads 512B
// contiguous per LDG.128, 4 batched. (Measured standalone: 24.4us.)
// NEVER WAITS — always makes forward progress.
// ============================================================================
__device__ __forceinline__ void score_role(
    const float* __restrict__ tokens, const float* __restrict__ norm_w,
    const float* __restrict__ fc_w, unsigned* __restrict__ keys,
    int b, int bx, char* sm)
{
    float*  wsh = (float*)sm;                 // 1KB
    float4* r1  = (float4*)(sm + 1024);       // 4KB
    float4* r2  = (float4*)(sm + 5120);       // 4KB
    float4* r3  = (float4*)(sm + 9216);       // 4KB
    float*  rw  = (float*)(sm + 13312);       // 1KB

    const int tid   = threadIdx.x;
    const int q     = tid & 63;
    const int split = tid >> 6;

    wsh[tid] = norm_w[tid] * fc_w[tid];
    __syncthreads();

    const int n4 = bx * 64 + q;
    const float4* p = (const float4*)(tokens + (size_t)b * DD * NN) + n4;

    float4 s1 = {0.f,0.f,0.f,0.f}, s2 = s1, sd = s1;
    float  sw = 0.f;
#pragma unroll
    for (int j0 = 0; j0 < 64; j0 += 4) {
        float4 x[4];
#pragma unroll
        for (int jj = 0; jj < 4; ++jj)
            x[jj] = p[(size_t)(split * 64 + j0 + jj) * (NN / 4)];
#pragma unroll
        for (int jj = 0; jj < 4; ++jj) {
            float w = wsh[split * 64 + j0 + jj];
            s1.x += x[jj].x;           s1.y += x[jj].y;
            s1.z += x[jj].z;           s1.w += x[jj].w;
            s2.x += x[jj].x * x[jj].x; s2.y += x[jj].y * x[jj].y;
            s2.z += x[jj].z * x[jj].z; s2.w += x[jj].w * x[jj].w;
            sd.x += x[jj].x * w;       sd.y += x[jj].y * w;
            sd.z += x[jj].z * w;       sd.w += x[jj].w * w;
            sw   += w;
        }
    }
    if (split != 0) {
        r1[split * 64 + q] = s1; r2[split * 64 + q] = s2;
        r3[split * 64 + q] = sd; rw[split * 64 + q] = sw;
    }
    __syncthreads();

    if (split == 0) {
#pragma unroll
        for (int s = 1; s < 4; ++s) {
            float4 a = r1[s * 64 + q], c = r2[s * 64 + q], d = r3[s * 64 + q];
            s1.x += a.x; s1.y += a.y; s1.z += a.z; s1.w += a.w;
            s2.x += c.x; s2.y += c.y; s2.z += c.z; s2.w += c.w;
            sd.x += d.x; sd.y += d.y; sd.z += d.z; sd.w += d.w;
            sw   += rw[s * 64 + q];
        }
        const float inv = 1.0f / (float)DD;
        uint4 kv;
        float mu, var;
        mu = s1.x*inv; var = fmaxf(s2.x*inv - mu*mu, 0.f);
        kv.x = f2k((sd.x - mu*sw) * rsqrtf(var + 1e-5f));
        mu = s1.y*inv; var = fmaxf(s2.y*inv - mu*mu, 0.f);
        kv.y = f2k((sd.y - mu*sw) * rsqrtf(var + 1e-5f));
        mu = s1.z*inv; var = fmaxf(s2.z*inv - mu*mu, 0.f);
        kv.z = f2k((sd.z - mu*sw) * rsqrtf(var + 1e-5f));
        mu = s1.w*inv; var = fmaxf(s2.w*inv - mu*mu, 0.f);
        kv.w = f2k((sd.w - mu*sw) * rsqrtf(var + 1e-5f));
        ((uint4*)keys)[b * (NN / 4) + n4] = kv;
    }
}

// ============================================================================
// ROLE 2: select — per-batch radix-select (KK-th largest) + rank compaction.
// 256 threads, 16 keys/thread. Warp-aggregated histogram atomics, parallel
// suffix-scan bin pick, packed shuffle-scan compaction. lax.top_k tie rules.
// ============================================================================
__device__ __forceinline__ void select_role(
    const unsigned* __restrict__ keys, int* __restrict__ pos, int b, char* sm)
{
    int*      hist     = (int*)sm;
    int*      wsum     = (int*)(sm + 1024);
    unsigned* s_prefix = (unsigned*)(sm + 1056);
    int*      s_R      = (int*)(sm + 1060);

    const int tid  = threadIdx.x;
    const int lane = tid & 31;
    const int wid  = tid >> 5;

    unsigned k[16];
#pragma unroll
    for (int i = 0; i < 4; ++i) {
        uint4 kv = ((const uint4*)(keys + b * NN))[tid * 4 + i];
        k[i*4+0] = kv.x; k[i*4+1] = kv.y; k[i*4+2] = kv.z; k[i*4+3] = kv.w;
    }
    if (tid == 0) { *s_prefix = 0u; *s_R = KK; }
    __syncthreads();

    unsigned mask = 0u;
    for (int shift = 24; shift >= 0; shift -= 8) {
        hist[tid] = 0;
        __syncthreads();
        const unsigned prefix = *s_prefix;
        const int      R      = *s_R;

#pragma unroll
        for (int j = 0; j < 16; ++j) {
            int bin = ((k[j] & mask) == prefix) ? (int)((k[j] >> shift) & 255u) : 256;
            unsigned mm  = __match_any_sync(0xFFFFFFFFu, bin);
            int      ldr = __ffs(mm) - 1;
            if (lane == ldr && bin < 256)
                atomicAdd(&hist[bin], __popc(mm));
        }
        __syncthreads();

        int c = hist[255 - tid];
        int v = c;
#pragma unroll
        for (int o = 1; o < 32; o <<= 1) {
            int t = __shfl_up_sync(0xFFFFFFFFu, v, o);
            if (lane >= o) v += t;
        }
        if (lane == 31) wsum[wid] = v;
        __syncthreads();
        int S = v;
#pragma unroll
        for (int w = 0; w < 7; ++w)
            if (w < wid) S += wsum[w];
        if (S >= R && S - c < R) {                 // unique boundary thread
            *s_prefix = prefix | ((unsigned)(255 - tid) << shift);
            *s_R      = R - (S - c);
        }
        mask |= 255u << shift;
        __syncthreads();
    }
    const unsigned T    = *s_prefix;
    const int      Rfin = *s_R;

    int cg = 0, ce = 0;
#pragma unroll
    for (int j = 0; j < 16; ++j) { cg += (k[j] > T); ce += (k[j] == T); }
    int myv = (cg << 16) | ce;
    int v = myv;
#pragma unroll
    for (int o = 1; o < 32; o <<= 1) {
        int t = __shfl_up_sync(0xFFFFFFFFu, v, o);
        if (lane >= o) v += t;
    }
    if (lane == 31) wsum[wid] = v;
    __syncthreads();
    if (wid == 0 && lane < 8) {
        int t = wsum[lane];
#pragma unroll
        for (int o = 1; o < 8; o <<= 1) {
            int u = __shfl_up_sync(0x000000FFu, t, o);
            if (lane >= o) t += u;
        }
        wsum[lane] = t;
    }
    __syncthreads();
    int pre = v - myv + (wid > 0 ? wsum[wid - 1] : 0);
    int g = pre >> 16;
    int e = pre & 0xFFFF;

    int vals[16];
#pragma unroll
    for (int j = 0; j < 16; ++j) {
        int kp = -1;
        if (k[j] > T)       { kp = g + min(e, Rfin); ++g; }
        else if (k[j] == T) { if (e < Rfin) kp = g + e; ++e; }
        vals[j] = kp;
    }
#pragma unroll
    for (int i = 0; i < 4; ++i) {
        int4 op = { vals[i*4+0], vals[i*4+1], vals[i*4+2], vals[i*4+3] };
        ((int4*)(pos + b * NN))[tid * 4 + i] = op;
    }
}

// ============================================================================
// Fused pipeline kernel. Block order per batch: [S(b)x16, Sel(b), G(b)x128].
// KEY DESIGN: gather blocks LOAD FIRST (reads depend only on tokens), THEN
// wait for select's flag, THEN write. Every resident block streams memory
// immediately -> score reads + gather reads + gather writes blend in DRAM,
// and the dependency wait is overlapped with the tile load + other blocks.
// Waits only target lower-indexed blocks; dispatch is index-ordered -> safe.
// ============================================================================
__global__ void __launch_bounds__(256)
pipeline_kernel(const float* __restrict__ tokens,
                const float* __restrict__ norm_w,
                const float* __restrict__ fc_w,
                unsigned*    __restrict__ keys,
                int*         __restrict__ pos,
                float*       __restrict__ out)
{
    // gather needs the largest smem: tile 256x33 floats (33792B) + spos 128B
    __shared__ __align__(16) char sm[33920];

    const int idx = blockIdx.x;
    const int b   = idx / BLKS_PER_B;
    const int r   = idx - b * BLKS_PER_B;
    const int tid = threadIdx.x;

    if (r < SCORE_BLKS) {
        score_role(tokens, norm_w, fc_w, keys, b, r, sm);
        __syncthreads();
        __threadfence();                              // release keys
        if (tid == 0) atomicAdd(&g_sync[b], 1);
        return;
    }
    if (r == SCORE_BLKS) {
        if (tid == 0)
            while (atomicAdd(&g_sync[b], 0) < SCORE_BLKS) __nanosleep(64);
        __syncthreads();
        __threadfence();                              // acquire keys
        select_role(keys, pos, b, sm);
        __syncthreads();
        __threadfence();                              // release pos
        if (tid == 0) atomicExch(&g_sync[32 + b], 1);
        return;
    }

    // -------- gather: LOAD (no dependency) -> WAIT -> WRITE --------
    float (*tile)[33] = (float(*)[33])sm;             // [d][token], pad 33
    int*   spos       = (int*)(sm + 33792);

    const int bx = r - SCORE_BLKS - 1;
    const int n0 = bx * 32;
    const int f  = tid & 7;                           // float4 slot (4 tokens)
    const int d0 = tid >> 3;                          // 0..31
    const float* base = tokens + (size_t)b * DD * NN + n0 + f * 4;

    // Load full 32-token x 256-d tile: 8 independent LDG.128 per thread.
    // These reads hit L2 hot (score(b) streamed them moments ago).
#pragma unroll
    for (int j = 0; j < 8; ++j) {
        int d = d0 + j * 32;
        float4 v = *(const float4*)(base + (size_t)d * NN);
        tile[d][f * 4 + 0] = v.x;
        tile[d][f * 4 + 1] = v.y;
        tile[d][f * 4 + 2] = v.z;
        tile[d][f * 4 + 3] = v.w;
    }

    // Wait for select(b) — overlapped with the tile load latency above.
    if (tid == 0)
        while (atomicAdd(&g_sync[32 + b], 0) == 0) __nanosleep(64);
    __syncthreads();
    __threadfence();                                  // acquire pos
    if (tid < 32) spos[tid] = pos[b * NN + n0 + tid];
    __syncthreads();

    // Write kept rows as contiguous 1KB lines (evict-first; never re-read).
    float* ob = out + (size_t)b * KK * DD;
#pragma unroll 4
    for (int kk = 0; kk < 32; ++kk) {
        int p = spos[kk];
        if (p >= 0)
            __stcs(&ob[(size_t)p * DD + tid], tile[tid][kk]);
    }
}

// ---------------------------------------------------------------------------
extern "C" void kernel_launch(void* const* d_in, const int* in_sizes, int n_in,
                              void* d_out, int out_size)
{
    const float* tokens = (const float*)d_in[0];
    const float* norm_w = (const float*)d_in[1];
    // d_in[2] = norm_b (order-irrelevant constant shift)
    const float* fc_w   = (const float*)d_in[3];
    // d_in[4] = fc_b   (order-irrelevant constant shift)
    float* out = (float*)d_out;

    unsigned* keys;
    int* pos;
    int* sync;
    cudaGetSymbolAddress((void**)&keys, g_keys);
    cudaGetSymbolAddress((void**)&pos,  g_pos);
    cudaGetSymbolAddress((void**)&sync, g_sync);

    cudaMemsetAsync(sync, 0, 64 * sizeof(int));       // reset pipeline state
    pipeline_kernel<<<BB * BLKS_PER_B, 256>>>(tokens, norm_w, fc_w,
                                              keys, pos, out);
}

// round 13
// speedup vs baseline: 2.6947x; 2.2520x over previous
#include <cuda_runtime.h>
#include <cuda_bf16.h>
#include <stdint.h>

// Problem constants (TokenSelector: B=32, D=256, H=W=64)
#define BB 32
#define DD 256
#define NN 4096          // H*W
#define KK 2048          // NN * KEEP_RATIO

// ---------------- scratch (device globals; no allocation allowed) ----------
__device__ unsigned g_keys[BB * NN];   // monotone-sortable score keys
__device__ int      g_pos [BB * NN];   // output row per token, -1 if dropped

// float -> monotone-increasing uint key
__device__ __forceinline__ unsigned f2k(float f) {
    unsigned u = __float_as_uint(f);
    return u ^ ((u >> 31) ? 0xFFFFFFFFu : 0x80000000u);
}

// ---------------------------------------------------------------------------
// Kernel 1: per-token ordering key.  score = rstd*(dot(x,w') - mu*sum(w'))
// (softmax / norm_b / fc_b are order-irrelevant).
// Thread owns a QUAD of 4 consecutive tokens over a 64-wide d-slice
// (4 splits). Warp = one d-slice x 32 quads -> 512B contiguous per LDG.128.
// grid (16, 32) = 512 blocks, block 256 -> single resident wave.
// (Measured: 24.4us @ 5.6TB/s read ceiling.)
// PDL: each block triggers after its keys store -> select/gather launch early.
// ---------------------------------------------------------------------------
__global__ void __launch_bounds__(256)
score_kernel(const float* __restrict__ tokens,
             const float* __restrict__ norm_w,
             const float* __restrict__ fc_w,
             unsigned*    __restrict__ keys)
{
    __shared__ float  wsh[DD];
    __shared__ float4 r1[4][64], r2[4][64], r3[4][64];
    __shared__ float  rw[4][64];

    const int tid   = threadIdx.x;
    const int q     = tid & 63;     // token-quad slot within block (0..63)
    const int split = tid >> 6;     // d-slice 0..3 (64 d's each)

    wsh[tid] = norm_w[tid] * fc_w[tid];
    __syncthreads();

    const int b  = blockIdx.y;
    const int n4 = blockIdx.x * 64 + q;            // quad index 0..1023
    const float4* p = (const float4*)(tokens + (size_t)b * DD * NN) + n4;

    float4 s1 = {0.f,0.f,0.f,0.f}, s2 = s1, sd = s1;
    float  sw = 0.f;
#pragma unroll
    for (int j0 = 0; j0 < 64; j0 += 4) {
        float4 x[4];
#pragma unroll
        for (int jj = 0; jj < 4; ++jj)             // 4 independent 16B LDGs
            x[jj] = p[(size_t)(split * 64 + j0 + jj) * (NN / 4)];
#pragma unroll
        for (int jj = 0; jj < 4; ++jj) {
            float w = wsh[split * 64 + j0 + jj];
            s1.x += x[jj].x;           s1.y += x[jj].y;
            s1.z += x[jj].z;           s1.w += x[jj].w;
            s2.x += x[jj].x * x[jj].x; s2.y += x[jj].y * x[jj].y;
            s2.z += x[jj].z * x[jj].z; s2.w += x[jj].w * x[jj].w;
            sd.x += x[jj].x * w;       sd.y += x[jj].y * w;
            sd.z += x[jj].z * w;       sd.w += x[jj].w * w;
            sw   += w;
        }
    }
    if (split != 0) {
        r1[split][q] = s1; r2[split][q] = s2; r3[split][q] = sd; rw[split][q] = sw;
    }
    __syncthreads();

    if (split == 0) {                               // 2 warps finalize 64 quads
#pragma unroll
        for (int s = 1; s < 4; ++s) {
            float4 a = r1[s][q], c = r2[s][q], d = r3[s][q];
            s1.x += a.x; s1.y += a.y; s1.z += a.z; s1.w += a.w;
            s2.x += c.x; s2.y += c.y; s2.z += c.z; s2.w += c.w;
            sd.x += d.x; sd.y += d.y; sd.z += d.z; sd.w += d.w;
            sw   += rw[s][q];
        }
        const float inv = 1.0f / (float)DD;
        uint4 kv;
        float mu, var;
        mu = s1.x*inv; var = fmaxf(s2.x*inv - mu*mu, 0.f);
        kv.x = f2k((sd.x - mu*sw) * rsqrtf(var + 1e-5f));
        mu = s1.y*inv; var = fmaxf(s2.y*inv - mu*mu, 0.f);
        kv.y = f2k((sd.y - mu*sw) * rsqrtf(var + 1e-5f));
        mu = s1.z*inv; var = fmaxf(s2.z*inv - mu*mu, 0.f);
        kv.z = f2k((sd.z - mu*sw) * rsqrtf(var + 1e-5f));
        mu = s1.w*inv; var = fmaxf(s2.w*inv - mu*mu, 0.f);
        kv.w = f2k((sd.w - mu*sw) * rsqrtf(var + 1e-5f));
        ((uint4*)keys)[b * (NN / 4) + n4] = kv;
    }
    __syncthreads();                 // keys store happens-before every trigger
    cudaTriggerProgrammaticLaunchCompletion();
}

// ---------------------------------------------------------------------------
// Kernel 2: per-batch radix-select (KK-th largest) + rank compaction.
// One block per batch, 1024 threads, keys in registers (uint4/thread).
// PDL: gridDepSync at entry (keys ready), trigger after pos stores.
// Ties: lowest indices win (lax.top_k semantics).
// ---------------------------------------------------------------------------
__global__ void __launch_bounds__(1024)
select_kernel(const unsigned* __restrict__ keys, int* __restrict__ pos)
{
    __shared__ int hist[256];
    __shared__ int wsum[32];
    __shared__ unsigned s_prefix;
    __shared__ int s_R;

    const int tid  = threadIdx.x;
    const int lane = tid & 31;
    const int wid  = tid >> 5;
    const int b    = blockIdx.x;

    cudaGridDependencySynchronize();               // wait: keys visible

    uint4 kv = ((const uint4*)(keys + b * NN))[tid];
    unsigned k[4] = {kv.x, kv.y, kv.z, kv.w};

    if (tid == 0) { s_prefix = 0u; s_R = KK; }
    __syncthreads();

    unsigned mask = 0u;
    for (int shift = 24; shift >= 0; shift -= 8) {
        if (tid < 256) hist[tid] = 0;
        __syncthreads();
        const unsigned prefix = s_prefix;
        const int      R      = s_R;

#pragma unroll
        for (int j = 0; j < 4; ++j) {
            int bin = ((k[j] & mask) == prefix) ? (int)((k[j] >> shift) & 255u) : 256;
            unsigned mm  = __match_any_sync(0xFFFFFFFFu, bin);
            int      ldr = __ffs(mm) - 1;
            if (lane == ldr && bin < 256)
                atomicAdd(&hist[bin], __popc(mm));
        }
        __syncthreads();

        if (tid < 256) {
            int c = hist[255 - tid];
            int v = c;
#pragma unroll
            for (int o = 1; o < 32; o <<= 1) {
                int t = __shfl_up_sync(0xFFFFFFFFu, v, o);
                if (lane >= o) v += t;
            }
            if (lane == 31) wsum[wid] = v;
            __syncthreads();
            int S = v;
#pragma unroll
            for (int w = 0; w < 7; ++w)
                if (w < wid) S += wsum[w];
            if (S >= R && S - c < R) {             // unique boundary thread
                s_prefix = prefix | ((unsigned)(255 - tid) << shift);
                s_R      = R - (S - c);
            }
        } else {
            __syncthreads();
        }
        mask |= 255u << shift;
        __syncthreads();
    }
    const unsigned T    = s_prefix;
    const int      Rfin = s_R;

    int cg = 0, ce = 0;
#pragma unroll
    for (int j = 0; j < 4; ++j) { cg += (k[j] > T); ce += (k[j] == T); }
    int myv = (cg << 16) | ce;
    int v = myv;
#pragma unroll
    for (int o = 1; o < 32; o <<= 1) {
        int t = __shfl_up_sync(0xFFFFFFFFu, v, o);
        if (lane >= o) v += t;
    }
    if (lane == 31) wsum[wid] = v;
    __syncthreads();
    if (wid == 0) {
        int t = wsum[lane];
#pragma unroll
        for (int o = 1; o < 32; o <<= 1) {
            int u = __shfl_up_sync(0xFFFFFFFFu, t, o);
            if (lane >= o) t += u;
        }
        wsum[lane] = t;
    }
    __syncthreads();
    int pre = v - myv + (wid > 0 ? wsum[wid - 1] : 0);
    int g = pre >> 16;
    int e = pre & 0xFFFF;

    int vals[4];
#pragma unroll
    for (int j = 0; j < 4; ++j) {
        int kp = -1;
        if (k[j] > T)       { kp = g + min(e, Rfin); ++g; }
        else if (k[j] == T) { if (e < Rfin) kp = g + e; ++e; }
        vals[j] = kp;
    }
    int4 op = { vals[0], vals[1], vals[2], vals[3] };
    ((int4*)(pos + b * NN))[tid] = op;

    __syncthreads();                 // pos store happens-before every trigger
    cudaTriggerProgrammaticLaunchCompletion();
}

// ---------------------------------------------------------------------------
// Kernel 3: streaming compaction-gather with PDL prefetch.
// Loads the FULL 32-token x 256-d tile FIRST (reads depend only on tokens,
// so they overlap score's tail + select), THEN cudaGridDependencySynchronize
// (pos ready), THEN writes kept rows as contiguous 1KB lines (__stcs).
// tile[256][33]: float4 stores and column reads both conflict-free.
// grid: (NN/32=128, BB), block 256. smem 34KB -> ~6 blocks/SM.
// ---------------------------------------------------------------------------
__global__ void __launch_bounds__(256)
gather_kernel(const float* __restrict__ tokens,
              const int* __restrict__ pos,
              float* __restrict__ out)
{
    __shared__ float tile[DD][33];
    __shared__ int   spos[32];

    const int tid = threadIdx.x;
    const int b   = blockIdx.y;
    const int n0  = blockIdx.x * 32;

    const int f  = tid & 7;                   // float4 slot (4 tokens)
    const int d0 = tid >> 3;                  // 0..31
    const float* base = tokens + (size_t)b * DD * NN + n0 + f * 4;

    // Prefetch full tile: 8 independent LDG.128 per thread (no dependency).
#pragma unroll
    for (int j = 0; j < 8; ++j) {
        int d = d0 + j * 32;
        float4 v = *(const float4*)(base + (size_t)d * NN);
        tile[d][f * 4 + 0] = v.x;
        tile[d][f * 4 + 1] = v.y;
        tile[d][f * 4 + 2] = v.z;
        tile[d][f * 4 + 3] = v.w;
    }

    cudaGridDependencySynchronize();          // wait: pos visible (select done)
    if (tid < 32) spos[tid] = pos[b * NN + n0 + tid];
    __syncthreads();

    float* ob = out + (size_t)b * KK * DD;
#pragma unroll 4
    for (int kk = 0; kk < 32; ++kk) {
        int p = spos[kk];
        if (p >= 0)
            __stcs(&ob[(size_t)p * DD + tid], tile[tid][kk]);
    }
}

// ---------------------------------------------------------------------------
static inline void launch_pdl(const void* func, dim3 grid, dim3 block,
                              void** args)
{
    cudaLaunchConfig_t cfg = {};
    cfg.gridDim  = grid;
    cfg.blockDim = block;
    cfg.dynamicSmemBytes = 0;
    cfg.stream = 0;
    cudaLaunchAttribute at[1];
    at[0].id = cudaLaunchAttributeProgrammaticStreamSerialization;
    at[0].val.programmaticStreamSerializationAllowed = 1;
    cfg.attrs = at;
    cfg.numAttrs = 1;
    cudaLaunchKernelExC(&cfg, func, args);
}

extern "C" void kernel_launch(void* const* d_in, const int* in_sizes, int n_in,
                              void* d_out, int out_size)
{
    const float* tokens = (const float*)d_in[0];
    const float* norm_w = (const float*)d_in[1];
    // d_in[2] = norm_b (order-irrelevant constant shift)
    const float* fc_w   = (const float*)d_in[3];
    // d_in[4] = fc_b   (order-irrelevant constant shift)
    float* out = (float*)d_out;

    unsigned* keys;
    int* pos;
    cudaGetSymbolAddress((void**)&keys, g_keys);
    cudaGetSymbolAddress((void**)&pos,  g_pos);

    // K1: plain launch
    score_kernel<<<dim3(NN / 256, BB), 256>>>(tokens, norm_w, fc_w, keys);

    // K2, K3: PDL — launch early, hardware-ordered via gridDepSync
    {
        void* a[2] = { (void*)&keys, (void*)&pos };
        launch_pdl((const void*)select_kernel, dim3(BB, 1, 1), dim3(1024, 1, 1), a);
    }
    {
        void* a[3] = { (void*)&tokens, (void*)&pos, (void*)&out };
        launch_pdl((const void*)gather_kernel, dim3(NN / 32, BB, 1), dim3(256, 1, 1), a);
    }
}

// round 14
// speedup vs baseline: 2.7000x; 1.0020x over previous
#include <cuda_runtime.h>
#include <cuda_bf16.h>
#include <stdint.h>

// Problem constants (TokenSelector: B=32, D=256, H=W=64)
#define BB 32
#define DD 256
#define NN 4096          // H*W
#define KK 2048          // NN * KEEP_RATIO
#define SCORE_BLKS 16    // score blocks per batch

// ---------------- scratch (device globals; no allocation allowed) ----------
__device__ unsigned g_keys[BB * NN];   // monotone-sortable score keys
__device__ int      g_pos [BB * NN];   // output row per token, -1 if dropped
__device__ int      g_cnt [BB];        // per-batch completion counters

// float -> monotone-increasing uint key
__device__ __forceinline__ unsigned f2k(float f) {
    unsigned u = __float_as_uint(f);
    return u ^ ((u >> 31) ? 0xFFFFFFFFu : 0x80000000u);
}

// ============================================================================
// Select role (256 threads, 16 keys/thread) — radix-select KK-th largest +
// rank compaction. Warp-aggregated histogram atomics, parallel suffix-scan
// bin pick, packed shuffle-scan compaction. lax.top_k tie rules (lowest
// indices win at threshold). Validated in R10. Runs as the TAIL of the last
// score block per batch (keys are L2-hot).
// ============================================================================
__device__ void select_role(const unsigned* __restrict__ keys,
                            int* __restrict__ pos, int b)
{
    __shared__ int      hist[256];
    __shared__ int      wsum[8];
    __shared__ unsigned s_prefix;
    __shared__ int      s_R;

    const int tid  = threadIdx.x;
    const int lane = tid & 31;
    const int wid  = tid >> 5;

    unsigned k[16];
#pragma unroll
    for (int i = 0; i < 4; ++i) {
        uint4 kv = ((const uint4*)(keys + b * NN))[tid * 4 + i];
        k[i*4+0] = kv.x; k[i*4+1] = kv.y; k[i*4+2] = kv.z; k[i*4+3] = kv.w;
    }
    if (tid == 0) { s_prefix = 0u; s_R = KK; }
    __syncthreads();

    unsigned mask = 0u;
    for (int shift = 24; shift >= 0; shift -= 8) {
        hist[tid] = 0;
        __syncthreads();
        const unsigned prefix = s_prefix;
        const int      R      = s_R;

#pragma unroll
        for (int j = 0; j < 16; ++j) {
            int bin = ((k[j] & mask) == prefix) ? (int)((k[j] >> shift) & 255u) : 256;
            unsigned mm  = __match_any_sync(0xFFFFFFFFu, bin);
            int      ldr = __ffs(mm) - 1;
            if (lane == ldr && bin < 256)
                atomicAdd(&hist[bin], __popc(mm));
        }
        __syncthreads();

        // suffix count S(bin) = #keys with bin' >= bin within prefix class
        int c = hist[255 - tid];
        int v = c;
#pragma unroll
        for (int o = 1; o < 32; o <<= 1) {
            int t = __shfl_up_sync(0xFFFFFFFFu, v, o);
            if (lane >= o) v += t;
        }
        if (lane == 31) wsum[wid] = v;
        __syncthreads();
        int S = v;
#pragma unroll
        for (int w = 0; w < 7; ++w)
            if (w < wid) S += wsum[w];
        if (S >= R && S - c < R) {                 // unique boundary thread
            s_prefix = prefix | ((unsigned)(255 - tid) << shift);
            s_R      = R - (S - c);
        }
        mask |= 255u << shift;
        __syncthreads();
    }
    const unsigned T    = s_prefix;
    const int      Rfin = s_R;

    int cg = 0, ce = 0;
#pragma unroll
    for (int j = 0; j < 16; ++j) { cg += (k[j] > T); ce += (k[j] == T); }
    int myv = (cg << 16) | ce;
    int v = myv;
#pragma unroll
    for (int o = 1; o < 32; o <<= 1) {
        int t = __shfl_up_sync(0xFFFFFFFFu, v, o);
        if (lane >= o) v += t;
    }
    if (lane == 31) wsum[wid] = v;
    __syncthreads();
    if (wid == 0 && lane < 8) {
        int t = wsum[lane];
#pragma unroll
        for (int o = 1; o < 8; o <<= 1) {
            int u = __shfl_up_sync(0x000000FFu, t, o);
            if (lane >= o) t += u;
        }
        wsum[lane] = t;
    }
    __syncthreads();
    int pre = v - myv + (wid > 0 ? wsum[wid - 1] : 0);
    int g = pre >> 16;
    int e = pre & 0xFFFF;

    int vals[16];
#pragma unroll
    for (int j = 0; j < 16; ++j) {
        int kp = -1;
        if (k[j] > T)       { kp = g + min(e, Rfin); ++g; }
        else if (k[j] == T) { if (e < Rfin) kp = g + e; ++e; }
        vals[j] = kp;
    }
#pragma unroll
    for (int i = 0; i < 4; ++i) {
        int4 op = { vals[i*4+0], vals[i*4+1], vals[i*4+2], vals[i*4+3] };
        ((int4*)(pos + b * NN))[tid * 4 + i] = op;
    }
}

// ---------------------------------------------------------------------------
// Kernel 1: score + fused last-block select.
// score = rstd*(dot(x,w') - mu*sum(w')) — softmax/norm_b/fc_b order-irrelevant.
// Thread owns a QUAD of 4 consecutive tokens over a 64-wide d-slice (4
// splits); warp reads 512B contiguous per LDG.128, 4 batched. grid (16,32) =
// 512 blocks -> single wave (launch_bounds min 4 blocks/SM guarantees it).
// The LAST score block of each batch (atomic counter) runs select_role as a
// tail while other batches still stream — hides the whole select phase.
// ---------------------------------------------------------------------------
__global__ void __launch_bounds__(256, 4)
score_kernel(const float* __restrict__ tokens,
             const float* __restrict__ norm_w,
             const float* __restrict__ fc_w,
             unsigned*    __restrict__ keys,
             int*         __restrict__ pos)
{
    __shared__ float  wsh[DD];
    __shared__ float4 r1[4][64], r2[4][64], r3[4][64];
    __shared__ float  rw[4][64];
    __shared__ int    s_last;

    const int tid   = threadIdx.x;
    const int q     = tid & 63;     // token-quad slot within block (0..63)
    const int split = tid >> 6;     // d-slice 0..3 (64 d's each)

    wsh[tid] = norm_w[tid] * fc_w[tid];
    __syncthreads();

    const int b  = blockIdx.y;
    const int n4 = blockIdx.x * 64 + q;            // quad index 0..1023
    const float4* p = (const float4*)(tokens + (size_t)b * DD * NN) + n4;

    float4 s1 = {0.f,0.f,0.f,0.f}, s2 = s1, sd = s1;
    float  sw = 0.f;
#pragma unroll
    for (int j0 = 0; j0 < 64; j0 += 4) {
        float4 x[4];
#pragma unroll
        for (int jj = 0; jj < 4; ++jj)             // 4 independent 16B LDGs
            x[jj] = p[(size_t)(split * 64 + j0 + jj) * (NN / 4)];
#pragma unroll
        for (int jj = 0; jj < 4; ++jj) {
            float w = wsh[split * 64 + j0 + jj];
            s1.x += x[jj].x;           s1.y += x[jj].y;
            s1.z += x[jj].z;           s1.w += x[jj].w;
            s2.x += x[jj].x * x[jj].x; s2.y += x[jj].y * x[jj].y;
            s2.z += x[jj].z * x[jj].z; s2.w += x[jj].w * x[jj].w;
            sd.x += x[jj].x * w;       sd.y += x[jj].y * w;
            sd.z += x[jj].z * w;       sd.w += x[jj].w * w;
            sw   += w;
        }
    }
    if (split != 0) {
        r1[split][q] = s1; r2[split][q] = s2; r3[split][q] = sd; rw[split][q] = sw;
    }
    __syncthreads();

    if (split == 0) {                               // 2 warps finalize 64 quads
#pragma unroll
        for (int s = 1; s < 4; ++s) {
            float4 a = r1[s][q], c = r2[s][q], d = r3[s][q];
            s1.x += a.x; s1.y += a.y; s1.z += a.z; s1.w += a.w;
            s2.x += c.x; s2.y += c.y; s2.z += c.z; s2.w += c.w;
            sd.x += d.x; sd.y += d.y; sd.z += d.z; sd.w += d.w;
            sw   += rw[s][q];
        }
        const float inv = 1.0f / (float)DD;
        uint4 kv;
        float mu, var;
        mu = s1.x*inv; var = fmaxf(s2.x*inv - mu*mu, 0.f);
        kv.x = f2k((sd.x - mu*sw) * rsqrtf(var + 1e-5f));
        mu = s1.y*inv; var = fmaxf(s2.y*inv - mu*mu, 0.f);
        kv.y = f2k((sd.y - mu*sw) * rsqrtf(var + 1e-5f));
        mu = s1.z*inv; var = fmaxf(s2.z*inv - mu*mu, 0.f);
        kv.z = f2k((sd.z - mu*sw) * rsqrtf(var + 1e-5f));
        mu = s1.w*inv; var = fmaxf(s2.w*inv - mu*mu, 0.f);
        kv.w = f2k((sd.w - mu*sw) * rsqrtf(var + 1e-5f));
        ((uint4*)keys)[b * (NN / 4) + n4] = kv;
    }

    // ---- last-block-per-batch runs select (threadFenceReduction pattern) ----
    __threadfence();                 // make this block's key stores visible
    __syncthreads();
    if (tid == 0) {
        int prev = atomicAdd(&g_cnt[b], 1);
        s_last = (prev == SCORE_BLKS - 1);
    }
    __syncthreads();
    if (s_last) {
        __threadfence();             // acquire: all 16 blocks' keys visible
        select_role(keys, pos, b);
    }
}

// ---------------------------------------------------------------------------
// Kernel 2: streaming compaction-gather (exact R5 config, 57.9us total).
// 32 tokens x D in two d-halves, 128x33 smem tile (17KB), float4 loads,
// conflict-free smem both directions, __stcs writes, reversed batch order.
// grid: (NN/32=128, BB), block 256.
// ---------------------------------------------------------------------------
__global__ void __launch_bounds__(256)
gather_kernel(const float* __restrict__ tokens,
              const int* __restrict__ pos,
              float* __restrict__ out)
{
    __shared__ float tile[128][33];
    __shared__ int   spos[32];

    const int tid = threadIdx.x;
    const int b   = (BB - 1) - blockIdx.y;    // hottest-in-L2 batches first
    const int n0  = blockIdx.x * 32;

    if (tid < 32) spos[tid] = pos[b * NN + n0 + tid];

    const int f  = tid & 7;                   // float4 slot (4 tokens)
    const int d0 = tid >> 3;                  // 0..31
    const float* base = tokens + (size_t)b * DD * NN + n0 + f * 4;
    float* ob = out + (size_t)b * KK * DD;

    const int kk2 = tid >> 7;                 // which of 2 rows this thread writes
    const int c   = tid & 127;                // column within 128-wide half

#pragma unroll
    for (int h = 0; h < 2; ++h) {
        __syncthreads();                      // tile reuse guard (and spos vis)
#pragma unroll
        for (int j = 0; j < 4; ++j) {         // 4 independent 16B LDGs
            int d = d0 + j * 32;              // local d within half
            float4 v = *(const float4*)(base + (size_t)(h * 128 + d) * NN);
            tile[d][f * 4 + 0] = v.x;
            tile[d][f * 4 + 1] = v.y;
            tile[d][f * 4 + 2] = v.z;
            tile[d][f * 4 + 3] = v.w;
        }
        __syncthreads();
#pragma unroll
        for (int pair = 0; pair < 16; ++pair) {
            int kk = pair * 2 + kk2;
            int p  = spos[kk];
            if (p >= 0)
                __stcs(&ob[(size_t)p * DD + h * 128 + c], tile[c][kk]);
        }
    }
}

// ---------------------------------------------------------------------------
extern "C" void kernel_launch(void* const* d_in, const int* in_sizes, int n_in,
                              void* d_out, int out_size)
{
    const float* tokens = (const float*)d_in[0];
    const float* norm_w = (const float*)d_in[1];
    // d_in[2] = norm_b (order-irrelevant constant shift)
    const float* fc_w   = (const float*)d_in[3];
    // d_in[4] = fc_b   (order-irrelevant constant shift)
    float* out = (float*)d_out;

    unsigned* keys;
    int* pos;
    int* cnt;
    cudaGetSymbolAddress((void**)&keys, g_keys);
    cudaGetSymbolAddress((void**)&pos,  g_pos);
    cudaGetSymbolAddress((void**)&cnt,  g_cnt);

    cudaMemsetAsync(cnt, 0, BB * sizeof(int));     // reset batch counters
    score_kernel<<<dim3(NN / 256, BB), 256>>>(tokens, norm_w, fc_w, keys, pos);
    gather_kernel<<<dim3(NN / 32, BB), 256>>>(tokens, pos, out);
}

// round 15
// speedup vs baseline: 2.8898x; 1.0703x over previous
#include <cuda_runtime.h>
#include <cuda_bf16.h>
#include <stdint.h>

// Problem constants (TokenSelector: B=32, D=256, H=W=64)
#define BB 32
#define DD 256
#define NN 4096          // H*W
#define KK 2048          // NN * KEEP_RATIO

// ---------------- scratch (device globals; no allocation allowed) ----------
__device__ unsigned g_keys[BB * NN];   // monotone-sortable score keys
__device__ int      g_pos [BB * NN];   // output row per token, -1 if dropped

// float -> monotone-increasing uint key
__device__ __forceinline__ unsigned f2k(float f) {
    unsigned u = __float_as_uint(f);
    return u ^ ((u >> 31) ? 0xFFFFFFFFu : 0x80000000u);
}

// ---------------------------------------------------------------------------
// Kernel 1: per-token ordering key.  score = rstd*(dot(x,w') - mu*sum(w'))
// (softmax / norm_b / fc_b are order-irrelevant).
// Thread owns a QUAD of 4 consecutive tokens over a 64-wide d-slice
// (4 splits). Warp = one d-slice x 32 quads -> 512B contiguous per LDG.128.
// grid (16, 32) = 512 blocks, block 256 -> single resident wave.
// (Exact R5 config: measured 24.4-24.9us.)
// ---------------------------------------------------------------------------
__global__ void __launch_bounds__(256)
score_kernel(const float* __restrict__ tokens,
             const float* __restrict__ norm_w,
             const float* __restrict__ fc_w,
             unsigned*    __restrict__ keys)
{
    __shared__ float  wsh[DD];
    __shared__ float4 r1[4][64], r2[4][64], r3[4][64];
    __shared__ float  rw[4][64];

    const int tid   = threadIdx.x;
    const int q     = tid & 63;     // token-quad slot within block (0..63)
    const int split = tid >> 6;     // d-slice 0..3 (64 d's each)

    wsh[tid] = norm_w[tid] * fc_w[tid];
    __syncthreads();

    const int b  = blockIdx.y;
    const int n4 = blockIdx.x * 64 + q;            // quad index 0..1023
    const float4* p = (const float4*)(tokens + (size_t)b * DD * NN) + n4;

    float4 s1 = {0.f,0.f,0.f,0.f}, s2 = s1, sd = s1;
    float  sw = 0.f;
#pragma unroll
    for (int j0 = 0; j0 < 64; j0 += 4) {
        float4 x[4];
#pragma unroll
        for (int jj = 0; jj < 4; ++jj)             // 4 independent 16B LDGs
            x[jj] = p[(size_t)(split * 64 + j0 + jj) * (NN / 4)];
#pragma unroll
        for (int jj = 0; jj < 4; ++jj) {
            float w = wsh[split * 64 + j0 + jj];
            s1.x += x[jj].x;           s1.y += x[jj].y;
            s1.z += x[jj].z;           s1.w += x[jj].w;
            s2.x += x[jj].x * x[jj].x; s2.y += x[jj].y * x[jj].y;
            s2.z += x[jj].z * x[jj].z; s2.w += x[jj].w * x[jj].w;
            sd.x += x[jj].x * w;       sd.y += x[jj].y * w;
            sd.z += x[jj].z * w;       sd.w += x[jj].w * w;
            sw   += w;
        }
    }
    if (split != 0) {
        r1[split][q] = s1; r2[split][q] = s2; r3[split][q] = sd; rw[split][q] = sw;
    }
    __syncthreads();

    if (split == 0) {                               // 2 warps finalize 64 quads
#pragma unroll
        for (int s = 1; s < 4; ++s) {
            float4 a = r1[s][q], c = r2[s][q], d = r3[s][q];
            s1.x += a.x; s1.y += a.y; s1.z += a.z; s1.w += a.w;
            s2.x += c.x; s2.y += c.y; s2.z += c.z; s2.w += c.w;
            sd.x += d.x; sd.y += d.y; sd.z += d.z; sd.w += d.w;
            sw   += rw[s][q];
        }
        const float inv = 1.0f / (float)DD;
        uint4 kv;
        float mu, var;
        mu = s1.x*inv; var = fmaxf(s2.x*inv - mu*mu, 0.f);
        kv.x = f2k((sd.x - mu*sw) * rsqrtf(var + 1e-5f));
        mu = s1.y*inv; var = fmaxf(s2.y*inv - mu*mu, 0.f);
        kv.y = f2k((sd.y - mu*sw) * rsqrtf(var + 1e-5f));
        mu = s1.z*inv; var = fmaxf(s2.z*inv - mu*mu, 0.f);
        kv.z = f2k((sd.z - mu*sw) * rsqrtf(var + 1e-5f));
        mu = s1.w*inv; var = fmaxf(s2.w*inv - mu*mu, 0.f);
        kv.w = f2k((sd.w - mu*sw) * rsqrtf(var + 1e-5f));
        ((uint4*)keys)[b * (NN / 4) + n4] = kv;
    }
}

// ---------------------------------------------------------------------------
// Kernel 2: per-batch radix-select (KK-th largest) + rank compaction.
// One block per batch, 1024 threads, keys in registers (uint4/thread).
// Warp-aggregated histogram atomics; parallel suffix-scan bin pick;
// packed warp-shuffle scan compaction. Ties: lowest indices win (lax.top_k).
// (Exact R5 config: ~4us.)
// ---------------------------------------------------------------------------
__global__ void __launch_bounds__(1024)
select_kernel(const unsigned* __restrict__ keys, int* __restrict__ pos)
{
    __shared__ int hist[256];
    __shared__ int wsum[32];
    __shared__ unsigned s_prefix;
    __shared__ int s_R;

    const int tid  = threadIdx.x;
    const int lane = tid & 31;
    const int wid  = tid >> 5;
    const int b    = blockIdx.x;

    uint4 kv = ((const uint4*)(keys + b * NN))[tid];
    unsigned k[4] = {kv.x, kv.y, kv.z, kv.w};

    if (tid == 0) { s_prefix = 0u; s_R = KK; }
    __syncthreads();

    unsigned mask = 0u;
    for (int shift = 24; shift >= 0; shift -= 8) {
        if (tid < 256) hist[tid] = 0;
        __syncthreads();
        const unsigned prefix = s_prefix;
        const int      R      = s_R;

#pragma unroll
        for (int j = 0; j < 4; ++j) {
            int bin = ((k[j] & mask) == prefix) ? (int)((k[j] >> shift) & 255u) : 256;
            unsigned mm  = __match_any_sync(0xFFFFFFFFu, bin);
            int      ldr = __ffs(mm) - 1;
            if (lane == ldr && bin < 256)
                atomicAdd(&hist[bin], __popc(mm));
        }
        __syncthreads();

        if (tid < 256) {
            int c = hist[255 - tid];
            int v = c;
#pragma unroll
            for (int o = 1; o < 32; o <<= 1) {
                int t = __shfl_up_sync(0xFFFFFFFFu, v, o);
                if (lane >= o) v += t;
            }
            if (lane == 31) wsum[wid] = v;
            __syncthreads();
            int S = v;
#pragma unroll
            for (int w = 0; w < 7; ++w)
                if (w < wid) S += wsum[w];
            if (S >= R && S - c < R) {           // unique boundary thread
                s_prefix = prefix | ((unsigned)(255 - tid) << shift);
                s_R      = R - (S - c);
            }
        } else {
            __syncthreads();
        }
        mask |= 255u << shift;
        __syncthreads();
    }
    const unsigned T    = s_prefix;
    const int      Rfin = s_R;

    int cg = 0, ce = 0;
#pragma unroll
    for (int j = 0; j < 4; ++j) { cg += (k[j] > T); ce += (k[j] == T); }
    int myv = (cg << 16) | ce;
    int v = myv;
#pragma unroll
    for (int o = 1; o < 32; o <<= 1) {
        int t = __shfl_up_sync(0xFFFFFFFFu, v, o);
        if (lane >= o) v += t;
    }
    if (lane == 31) wsum[wid] = v;
    __syncthreads();
    if (wid == 0) {
        int t = wsum[lane];
#pragma unroll
        for (int o = 1; o < 32; o <<= 1) {
            int u = __shfl_up_sync(0xFFFFFFFFu, t, o);
            if (lane >= o) t += u;
        }
        wsum[lane] = t;
    }
    __syncthreads();
    int pre = v - myv + (wid > 0 ? wsum[wid - 1] : 0);
    int g = pre >> 16;
    int e = pre & 0xFFFF;

    int vals[4];
#pragma unroll
    for (int j = 0; j < 4; ++j) {
        int kp = -1;
        if (k[j] > T)       { kp = g + min(e, Rfin); ++g; }
        else if (k[j] == T) { if (e < Rfin) kp = g + e; ++e; }
        vals[j] = kp;
    }
    int4 op = { vals[0], vals[1], vals[2], vals[3] };
    ((int4*)(pos + b * NN))[tid] = op;
}

// ---------------------------------------------------------------------------
// Kernel 3: streaming compaction-gather (R5 structure). 32 tokens x D in two
// d-halves, 128x33 smem tile (17KB), float4 loads, conflict-free both ways.
// SINGLE CHANGE vs R5: writes use __stwt (write-through, NO L2 ALLOCATION)
// instead of __stcs. ~94% of the token array is still L2-resident from
// score; __stcs write-allocations were evicting it (only ~18% read hits).
// Write-through keeps the 67MB output out of L2 entirely -> gather reads
// hit the resident tokens at L2 bandwidth. Full 128B warp-contiguous lines,
// so write-through costs no RMW.
// grid: (NN/32=128, BB), block 256.
// ---------------------------------------------------------------------------
__global__ void __launch_bounds__(256)
gather_kernel(const float* __restrict__ tokens,
              const int* __restrict__ pos,
              float* __restrict__ out)
{
    __shared__ float tile[128][33];
    __shared__ int   spos[32];

    const int tid = threadIdx.x;
    const int b   = (BB - 1) - blockIdx.y;    // hottest-in-L2 batches first
    const int n0  = blockIdx.x * 32;

    if (tid < 32) spos[tid] = pos[b * NN + n0 + tid];

    const int f  = tid & 7;                   // float4 slot (4 tokens)
    const int d0 = tid >> 3;                  // 0..31
    const float* base = tokens + (size_t)b * DD * NN + n0 + f * 4;
    float* ob = out + (size_t)b * KK * DD;

    const int kk2 = tid >> 7;                 // which of 2 rows this thread writes
    const int c   = tid & 127;                // column within 128-wide half

#pragma unroll
    for (int h = 0; h < 2; ++h) {
        __syncthreads();                      // tile reuse guard (and spos vis)
#pragma unroll
        for (int j = 0; j < 4; ++j) {         // 4 independent 16B LDGs
            int d = d0 + j * 32;              // local d within half
            float4 v = *(const float4*)(base + (size_t)(h * 128 + d) * NN);
            tile[d][f * 4 + 0] = v.x;
            tile[d][f * 4 + 1] = v.y;
            tile[d][f * 4 + 2] = v.z;
            tile[d][f * 4 + 3] = v.w;
        }
        __syncthreads();
#pragma unroll
        for (int pair = 0; pair < 16; ++pair) {
            int kk = pair * 2 + kk2;
            int p  = spos[kk];
            if (p >= 0)
                __stwt(&ob[(size_t)p * DD + h * 128 + c], tile[c][kk]);
        }
    }
}

// ---------------------------------------------------------------------------
extern "C" void kernel_launch(void* const* d_in, const int* in_sizes, int n_in,
                              void* d_out, int out_size)
{
    const float* tokens = (const float*)d_in[0];
    const float* norm_w = (const float*)d_in[1];
    // d_in[2] = norm_b (order-irrelevant constant shift)
    const float* fc_w   = (const float*)d_in[3];
    // d_in[4] = fc_b   (order-irrelevant constant shift)
    float* out = (float*)d_out;

    unsigned* keys;
    int* pos;
    cudaGetSymbolAddress((void**)&keys, g_keys);
    cudaGetSymbolAddress((void**)&pos,  g_pos);

    score_kernel<<<dim3(NN / 256, BB), 256>>>(tokens, norm_w, fc_w, keys);
    select_kernel<<<BB, 1024>>>(keys, pos);
    gather_kernel<<<dim3(NN / 32, BB), 256>>>(tokens, pos, out);
}

// round 16
// speedup vs baseline: 2.9439x; 1.0187x over previous
#include <cuda_runtime.h>
#include <cuda_bf16.h>
#include <stdint.h>

// Problem constants (TokenSelector: B=32, D=256, H=W=64)
#define BB 32
#define DD 256
#define NN 4096          // H*W
#define KK 2048          // NN * KEEP_RATIO

// ---------------- scratch (device globals; no allocation allowed) ----------
__device__ unsigned g_keys[BB * NN];   // monotone-sortable score keys
__device__ int      g_pos [BB * NN];   // output row per token, -1 if dropped

// float -> monotone-increasing uint key
__device__ __forceinline__ unsigned f2k(float f) {
    unsigned u = __float_as_uint(f);
    return u ^ ((u >> 31) ? 0xFFFFFFFFu : 0x80000000u);
}

// ---------------------------------------------------------------------------
// Kernel 1: per-token ordering key.  score = rstd*(dot(x,w') - mu*sum(w'))
// (softmax / norm_b / fc_b are order-irrelevant).
// Thread owns a QUAD of 4 consecutive tokens over a 64-wide d-slice
// (4 splits). Warp = one d-slice x 32 quads -> 512B contiguous per LDG.128.
// grid (16, 32) = 512 blocks, block 256 -> single resident wave.
// (Exact R5 memory pattern; 32-bit index arithmetic only.)
// ---------------------------------------------------------------------------
__global__ void __launch_bounds__(256)
score_kernel(const float* __restrict__ tokens,
             const float* __restrict__ norm_w,
             const float* __restrict__ fc_w,
             unsigned*    __restrict__ keys)
{
    __shared__ float  wsh[DD];
    __shared__ float4 r1[4][64], r2[4][64], r3[4][64];
    __shared__ float  rw[4][64];

    const int tid   = threadIdx.x;
    const int q     = tid & 63;     // token-quad slot within block (0..63)
    const int split = tid >> 6;     // d-slice 0..3 (64 d's each)

    wsh[tid] = norm_w[tid] * fc_w[tid];
    __syncthreads();

    const unsigned b  = blockIdx.y;
    const unsigned n4 = blockIdx.x * 64u + (unsigned)q;   // quad index 0..1023
    // 32-bit element offsets: max index = 32*256*1024 float4 = 8.4M, fits.
    const float4* p = (const float4*)tokens + (b * (DD * (NN / 4)) + n4);

    float4 s1 = {0.f,0.f,0.f,0.f}, s2 = s1, sd = s1;
    float  sw = 0.f;
#pragma unroll
    for (int j0 = 0; j0 < 64; j0 += 4) {
        float4 x[4];
#pragma unroll
        for (int jj = 0; jj < 4; ++jj)             // 4 independent 16B LDGs
            x[jj] = p[(unsigned)(split * 64 + j0 + jj) * (NN / 4u)];
#pragma unroll
        for (int jj = 0; jj < 4; ++jj) {
            float w = wsh[split * 64 + j0 + jj];
            s1.x += x[jj].x;           s1.y += x[jj].y;
            s1.z += x[jj].z;           s1.w += x[jj].w;
            s2.x += x[jj].x * x[jj].x; s2.y += x[jj].y * x[jj].y;
            s2.z += x[jj].z * x[jj].z; s2.w += x[jj].w * x[jj].w;
            sd.x += x[jj].x * w;       sd.y += x[jj].y * w;
            sd.z += x[jj].z * w;       sd.w += x[jj].w * w;
            sw   += w;
        }
    }
    if (split != 0) {
        r1[split][q] = s1; r2[split][q] = s2; r3[split][q] = sd; rw[split][q] = sw;
    }
    __syncthreads();

    if (split == 0) {                               // 2 warps finalize 64 quads
#pragma unroll
        for (int s = 1; s < 4; ++s) {
            float4 a = r1[s][q], c = r2[s][q], d = r3[s][q];
            s1.x += a.x; s1.y += a.y; s1.z += a.z; s1.w += a.w;
            s2.x += c.x; s2.y += c.y; s2.z += c.z; s2.w += c.w;
            sd.x += d.x; sd.y += d.y; sd.z += d.z; sd.w += d.w;
            sw   += rw[s][q];
        }
        const float inv = 1.0f / (float)DD;
        uint4 kv;
        float mu, var;
        mu = s1.x*inv; var = fmaxf(s2.x*inv - mu*mu, 0.f);
        kv.x = f2k((sd.x - mu*sw) * rsqrtf(var + 1e-5f));
        mu = s1.y*inv; var = fmaxf(s2.y*inv - mu*mu, 0.f);
        kv.y = f2k((sd.y - mu*sw) * rsqrtf(var + 1e-5f));
        mu = s1.z*inv; var = fmaxf(s2.z*inv - mu*mu, 0.f);
        kv.z = f2k((sd.z - mu*sw) * rsqrtf(var + 1e-5f));
        mu = s1.w*inv; var = fmaxf(s2.w*inv - mu*mu, 0.f);
        kv.w = f2k((sd.w - mu*sw) * rsqrtf(var + 1e-5f));
        ((uint4*)keys)[b * (NN / 4u) + n4] = kv;
    }
}

// ---------------------------------------------------------------------------
// Kernel 2: per-batch radix-select (KK-th largest) + rank compaction.
// One block per batch, 1024 threads, keys in registers (uint4/thread).
// Warp-aggregated histogram atomics; parallel suffix-scan bin pick;
// packed warp-shuffle scan compaction. Ties: lowest indices win (lax.top_k).
// (Exact R5 version: ~4us.)
// ---------------------------------------------------------------------------
__global__ void __launch_bounds__(1024)
select_kernel(const unsigned* __restrict__ keys, int* __restrict__ pos)
{
    __shared__ int hist[256];
    __shared__ int wsum[32];
    __shared__ unsigned s_prefix;
    __shared__ int s_R;

    const int tid  = threadIdx.x;
    const int lane = tid & 31;
    const int wid  = tid >> 5;
    const int b    = blockIdx.x;

    uint4 kv = ((const uint4*)(keys + b * NN))[tid];
    unsigned k[4] = {kv.x, kv.y, kv.z, kv.w};

    if (tid == 0) { s_prefix = 0u; s_R = KK; }
    __syncthreads();

    unsigned mask = 0u;
    for (int shift = 24; shift >= 0; shift -= 8) {
        if (tid < 256) hist[tid] = 0;
        __syncthreads();
        const unsigned prefix = s_prefix;
        const int      R      = s_R;

#pragma unroll
        for (int j = 0; j < 4; ++j) {
            int bin = ((k[j] & mask) == prefix) ? (int)((k[j] >> shift) & 255u) : 256;
            unsigned mm  = __match_any_sync(0xFFFFFFFFu, bin);
            int      ldr = __ffs(mm) - 1;
            if (lane == ldr && bin < 256)
                atomicAdd(&hist[bin], __popc(mm));
        }
        __syncthreads();

        if (tid < 256) {
            int c = hist[255 - tid];
            int v = c;
#pragma unroll
            for (int o = 1; o < 32; o <<= 1) {
                int t = __shfl_up_sync(0xFFFFFFFFu, v, o);
                if (lane >= o) v += t;
            }
            if (lane == 31) wsum[wid] = v;
            __syncthreads();
            int S = v;
#pragma unroll
            for (int w = 0; w < 7; ++w)
                if (w < wid) S += wsum[w];
            if (S >= R && S - c < R) {           // unique boundary thread
                s_prefix = prefix | ((unsigned)(255 - tid) << shift);
                s_R      = R - (S - c);
            }
        } else {
            __syncthreads();
        }
        mask |= 255u << shift;
        __syncthreads();
    }
    const unsigned T    = s_prefix;
    const int      Rfin = s_R;

    int cg = 0, ce = 0;
#pragma unroll
    for (int j = 0; j < 4; ++j) { cg += (k[j] > T); ce += (k[j] == T); }
    int myv = (cg << 16) | ce;
    int v = myv;
#pragma unroll
    for (int o = 1; o < 32; o <<= 1) {
        int t = __shfl_up_sync(0xFFFFFFFFu, v, o);
        if (lane >= o) v += t;
    }
    if (lane == 31) wsum[wid] = v;
    __syncthreads();
    if (wid == 0) {
        int t = wsum[lane];
#pragma unroll
        for (int o = 1; o < 32; o <<= 1) {
            int u = __shfl_up_sync(0xFFFFFFFFu, t, o);
            if (lane >= o) t += u;
        }
        wsum[lane] = t;
    }
    __syncthreads();
    int pre = v - myv + (wid > 0 ? wsum[wid - 1] : 0);
    int g = pre >> 16;
    int e = pre & 0xFFFF;

    int vals[4];
#pragma unroll
    for (int j = 0; j < 4; ++j) {
        int kp = -1;
        if (k[j] > T)       { kp = g + min(e, Rfin); ++g; }
        else if (k[j] == T) { if (e < Rfin) kp = g + e; ++e; }
        vals[j] = kp;
    }
    int4 op = { vals[0], vals[1], vals[2], vals[3] };
    ((int4*)(pos + b * NN))[tid] = op;
}

// ---------------------------------------------------------------------------
// Kernel 3: streaming compaction-gather (exact R5 memory pattern: two
// ascending d-halves, 128x33 tile, plain float4 reads, __stcs writes,
// reversed batch order). ONLY change: 32-bit index arithmetic — spos holds
// PRE-SCALED element offsets (p*DD, computed once by 32 threads), killing
// the per-iteration 64-bit MAD chain that showed alu=24.7% in ncu.
// grid: (NN/32=128, BB), block 256.
// ---------------------------------------------------------------------------
__global__ void __launch_bounds__(256)
gather_kernel(const float* __restrict__ tokens,
              const int* __restrict__ pos,
              float* __restrict__ out)
{
    __shared__ float tile[128][33];
    __shared__ int   spos[32];      // pre-scaled: p*DD, or <0 if dropped

    const int tid = threadIdx.x;
    const int b   = (BB - 1) - blockIdx.y;    // hottest-in-L2 batches first
    const int n0  = blockIdx.x * 32;

    if (tid < 32) {
        int p = pos[b * NN + n0 + tid];
        spos[tid] = (p >= 0) ? p * DD : -1;   // pre-scale once
    }

    const int f  = tid & 7;                   // float4 slot (4 tokens)
    const int d0 = tid >> 3;                  // 0..31
    const float* base = tokens + (unsigned)(b * (DD * NN)) + (unsigned)(n0 + f * 4);
    float* ob = out + (unsigned)(b * (KK * DD));

    const int kk2 = tid >> 7;                 // which of 2 rows this thread writes
    const int c   = tid & 127;                // column within 128-wide half

#pragma unroll
    for (int h = 0; h < 2; ++h) {
        __syncthreads();                      // tile reuse guard (and spos vis)
        const unsigned hbase = (unsigned)(h * 128) * NN;
#pragma unroll
        for (int j = 0; j < 4; ++j) {         // 4 independent 16B LDGs
            int d = d0 + j * 32;              // local d within half
            float4 v = *(const float4*)(base + hbase + (unsigned)d * NN);
            tile[d][f * 4 + 0] = v.x;
            tile[d][f * 4 + 1] = v.y;
            tile[d][f * 4 + 2] = v.z;
            tile[d][f * 4 + 3] = v.w;
        }
        __syncthreads();
        float* obh = ob + (unsigned)(h * 128 + c);
#pragma unroll
        for (int pair = 0; pair < 16; ++pair) {
            int kk = pair * 2 + kk2;
            int po = spos[kk];                // pre-scaled p*DD
            if (po >= 0)
                __stcs(obh + (unsigned)po, tile[c][kk]);
        }
    }
}

// ---------------------------------------------------------------------------
extern "C" void kernel_launch(void* const* d_in, const int* in_sizes, int n_in,
                              void* d_out, int out_size)
{
    const float* tokens = (const float*)d_in[0];
    const float* norm_w = (const float*)d_in[1];
    // d_in[2] = norm_b (order-irrelevant constant shift)
    const float* fc_w   = (const float*)d_in[3];
    // d_in[4] = fc_b   (order-irrelevant constant shift)
    float* out = (float*)d_out;

    unsigned* keys;
    int* pos;
    cudaGetSymbolAddress((void**)&keys, g_keys);
    cudaGetSymbolAddress((void**)&pos,  g_pos);

    score_kernel<<<dim3(NN / 256, BB), 256>>>(tokens, norm_w, fc_w, keys);
    select_kernel<<<BB, 1024>>>(keys, pos);
    gather_kernel<<<dim3(NN / 32, BB), 256>>>(tokens, pos, out);
}